// round 13
// baseline (speedup 1.0000x reference)
#include <cuda_runtime.h>
#include <cuda_bf16.h>
#include <math.h>

// ---------------- problem constants ----------------
#define B_    1024
#define KNB   20
#define DN    172
#define DE    172
#define DT    100
#define QD    272          // DN + DT
#define KDIM  444          // DN + DE + DT
#define HD    136          // QD / 2 heads
#define NH    2
#define M1T   (B_ + B_*KNB)        // 21504 rows for layer-1 (both calls merged)
#define R1T   (M1T*KNB)            // 430080 kv rows
#define M2T   B_
#define R2T   (B_*KNB)             // 20480

// ---------------- scratch (device globals; no allocation allowed) ----------------
__device__ float g_kvout[(size_t)R1T * (2*QD)];   // K|V concat, 544 per row (~936 MB)
__device__ float g_wkv[KDIM * 2*QD];              // [Wk|Wv] concat per layer
__device__ float g_qin[(size_t)M1T * QD];         // layer-1 q_in (also residual + nf)
__device__ float g_q[(size_t)M1T * QD];
__device__ float g_attout[(size_t)M1T * QD];
__device__ float g_x[(size_t)M1T * QD];
__device__ float g_h[(size_t)M1T * DN];
__device__ float g_l1out[(size_t)M1T * DN];       // layer-1 conv output (kept for layer 2)
__device__ float g_qin2[(size_t)M2T * QD];

// ---------------- gather descriptor for the fused KV GEMM ----------------
struct KvGather {
    const float* memories;
    const float* node_raw;
    const float* edge_raw;
    const float* conv_rows;   // layer 2: conv features come from here (row r)
    const int*   ids1;  const int*   ids2;    // neighbor ids  (split by m)
    const int*   eids1; const int*   eids2;   // edge ids
    const float* nt1;   const float* nt2;     // neighbor times
    const float* t1;    const float* t2;      // center times
    const float* time_w; const float* time_b;
    int split_m;
};

struct GemmP {
    int M, N, Kd;
    const float* A;  int lda;      // MODE 0 / MODE 2 first part
    const float* A2; int lda2; int split;   // MODE 2 second part
    const float* Bm; int ldb;      // weights, Kd x N row-major
    float* C; int ldc;
    const float* bias;             // may be null
    const float* res; int ldres;   // may be null
    int relu;
    KvGather g;                    // MODE 1
};

__device__ __forceinline__ float kv_elem(const KvGather& g, int r, int k) {
    int m = r / KNB;
    if (k < DN) {
        if (g.conv_rows) return g.conv_rows[(size_t)r * DN + k];
        int id = (m < g.split_m) ? g.ids1[r] : g.ids2[r - g.split_m * KNB];
        return g.memories[(size_t)id * DN + k] + g.node_raw[(size_t)id * DN + k];
    } else if (k < DN + DE) {
        int eid = (m < g.split_m) ? g.eids1[r] : g.eids2[r - g.split_m * KNB];
        return g.edge_raw[(size_t)eid * DE + (k - DN)];
    } else {
        float tc = (m < g.split_m) ? g.t1[m] : g.t2[m - g.split_m];
        float tn = (m < g.split_m) ? g.nt1[r] : g.nt2[r - g.split_m * KNB];
        float dt = tc - tn;
        int j = k - DN - DE;
        return cosf(dt * g.time_w[j] + g.time_b[j]);
    }
}

template<int MODE>
__device__ __forceinline__ float load_a(const GemmP& p, int row, int k) {
    if (MODE == 0) return p.A[(size_t)row * p.lda + k];
    if (MODE == 2) return (k < p.split) ? p.A[(size_t)row * p.lda + k]
                                        : p.A2[(size_t)row * p.lda2 + (k - p.split)];
    return kv_elem(p.g, row, k);   // MODE 1
}

// ---------------- tf32 tensor-core GEMM ----------------
__device__ __forceinline__ unsigned f2tf32(float x) {
    unsigned u;
    asm("cvt.rna.tf32.f32 %0, %1;" : "=r"(u) : "f"(x));
    return u;
}

__device__ __forceinline__ void mma8(float* c, const unsigned* a, const unsigned* b) {
    asm volatile(
        "mma.sync.aligned.m16n8k8.row.col.f32.tf32.tf32.f32 "
        "{%0,%1,%2,%3}, {%4,%5,%6,%7}, {%8,%9}, {%0,%1,%2,%3};"
        : "+f"(c[0]), "+f"(c[1]), "+f"(c[2]), "+f"(c[3])
        : "r"(a[0]), "r"(a[1]), "r"(a[2]), "r"(a[3]), "r"(b[0]), "r"(b[1]));
}

template<int MODE>
__device__ __forceinline__ void g_fetch(const GemmP& p, int kt, int arow, bool aok,
                                        int bcol, bool cok, int fkb,
                                        float* areg, float* breg) {
#pragma unroll
    for (int i = 0; i < 8; i++) {
        int k = kt * 16 + fkb + i;
        bool kok = k < p.Kd;
        areg[i] = (kok && aok) ? load_a<MODE>(p, arow, k) : 0.f;
        breg[i] = (kok && cok) ? p.Bm[(size_t)k * p.ldb + bcol] : 0.f;
    }
}

__device__ __forceinline__ void s_store(unsigned A[16][136], unsigned Bsh[16][136],
                                        int fkb, int fm,
                                        const float* areg, const float* breg) {
#pragma unroll
    for (int i = 0; i < 8; i++) {
        A[fkb + i][fm]   = f2tf32(areg[i]);
        Bsh[fkb + i][fm] = f2tf32(breg[i]);
    }
}

// 128x128x16 block tile, 256 threads (8 warps, 2x4), warp tile 64x32 of m16n8k8.
template<int MODE>
__global__ __launch_bounds__(256) void mma_gemm_k(GemmP p) {
    __shared__ unsigned As[2][16][136];
    __shared__ unsigned Bs[2][16][136];
    const int tid  = threadIdx.x;
    const int bm   = blockIdx.y * 128;
    const int bn   = blockIdx.x * 128;
    const int warp = tid >> 5, lane = tid & 31;
    const int wm = warp >> 2, wn = warp & 3;
    const int gid = lane >> 2, qid = lane & 3;
    const int fm  = tid & 127;
    const int fkb = (tid >> 7) << 3;          // 0 or 8

    float acc[4][4][4];
#pragma unroll
    for (int i = 0; i < 4; i++)
#pragma unroll
        for (int j = 0; j < 4; j++)
#pragma unroll
            for (int r = 0; r < 4; r++) acc[i][j][r] = 0.f;

    const int arow = bm + fm;
    const int bcol = bn + fm;
    const bool aok = arow < p.M;
    const bool cok = bcol < p.N;
    const int nkt = (p.Kd + 15) >> 4;

    float areg[8], breg[8];
    g_fetch<MODE>(p, 0, arow, aok, bcol, cok, fkb, areg, breg);
    s_store(As[0], Bs[0], fkb, fm, areg, breg);
    __syncthreads();

    for (int kt = 0; kt < nkt; kt++) {
        const int buf = kt & 1;
        if (kt + 1 < nkt)
            g_fetch<MODE>(p, kt + 1, arow, aok, bcol, cok, fkb, areg, breg);

#pragma unroll
        for (int ks = 0; ks < 2; ks++) {
            unsigned af[4][4], bf[4][2];
#pragma unroll
            for (int mt = 0; mt < 4; mt++) {
                int m0 = wm * 64 + mt * 16 + gid;
                af[mt][0] = As[buf][ks * 8 + qid    ][m0];
                af[mt][1] = As[buf][ks * 8 + qid    ][m0 + 8];
                af[mt][2] = As[buf][ks * 8 + qid + 4][m0];
                af[mt][3] = As[buf][ks * 8 + qid + 4][m0 + 8];
            }
#pragma unroll
            for (int nt = 0; nt < 4; nt++) {
                int n0 = wn * 32 + nt * 8 + gid;
                bf[nt][0] = Bs[buf][ks * 8 + qid    ][n0];
                bf[nt][1] = Bs[buf][ks * 8 + qid + 4][n0];
            }
#pragma unroll
            for (int mt = 0; mt < 4; mt++)
#pragma unroll
                for (int nt = 0; nt < 4; nt++)
                    mma8(acc[mt][nt], af[mt], bf[nt]);
        }

        if (kt + 1 < nkt) {
            s_store(As[buf ^ 1], Bs[buf ^ 1], fkb, fm, areg, breg);
            __syncthreads();
        }
    }

    // epilogue: c0/c1 = (row gid, cols 2q,2q+1); c2/c3 = row gid+8
#pragma unroll
    for (int mt = 0; mt < 4; mt++) {
#pragma unroll
        for (int half = 0; half < 2; half++) {
            int row = bm + wm * 64 + mt * 16 + gid + half * 8;
            if (row >= p.M) continue;
#pragma unroll
            for (int nt = 0; nt < 4; nt++) {
                int col = bn + wn * 32 + nt * 8 + 2 * qid;
                if (col >= p.N) continue;        // N is even, so col+1 < N too
                float v0 = acc[mt][nt][half * 2 + 0];
                float v1 = acc[mt][nt][half * 2 + 1];
                if (p.bias) { v0 += p.bias[col]; v1 += p.bias[col + 1]; }
                if (p.res)  { v0 += p.res[(size_t)row * p.ldres + col];
                              v1 += p.res[(size_t)row * p.ldres + col + 1]; }
                if (p.relu) { v0 = fmaxf(v0, 0.f); v1 = fmaxf(v1, 0.f); }
                *reinterpret_cast<float2*>(&p.C[(size_t)row * p.ldc + col]) =
                    make_float2(v0, v1);
            }
        }
    }
}

// ---------------- small kernels ----------------
__global__ void concat_wkv_k(const float* Wk, const float* Wv, float* dst) {
    int idx = blockIdx.x * 256 + threadIdx.x;
    if (idx >= KDIM * 2 * QD) return;
    int k = idx / (2 * QD), n = idx % (2 * QD);
    dst[idx] = (n < QD) ? Wk[(size_t)k * QD + n] : Wv[(size_t)k * QD + (n - QD)];
}

__global__ void build_qin1_k(const float* mem, const float* raw,
                             const int* node_ids, const int* n1_ids,
                             const float* time_b, float* qin) {
    int m = blockIdx.x, c = threadIdx.x;   // 272 threads
    int id = (m < B_) ? node_ids[m] : n1_ids[m - B_];
    float v;
    if (c < DN) v = mem[(size_t)id * DN + c] + raw[(size_t)id * DN + c];
    else        v = cosf(time_b[c - DN]);
    qin[(size_t)m * QD + c] = v;
}

__global__ void build_qin2_k(const float* l1out, const float* time_b, float* qin) {
    int m = blockIdx.x, c = threadIdx.x;
    qin[(size_t)m * QD + c] = (c < DN) ? l1out[(size_t)m * DN + c]
                                       : cosf(time_b[c - DN]);
}

struct AttnP {
    const float* q;    // M x 272
    const float* kv;   // (M*20) x 544
    float* out;        // M x 272
    const int* ids1; const int* ids2; int split_m;
};

__global__ __launch_bounds__(256) void attn_k(AttnP p) {
    const float SCALE = 0.08574929257125441669f;   // 136^-0.5
    int m = blockIdx.x;
    __shared__ float sq[QD];
    __shared__ float sscore[NH][KNB];
    __shared__ float satt[NH][KNB];
    int tid = threadIdx.x;
    for (int c = tid; c < QD; c += 256) sq[c] = p.q[(size_t)m * QD + c];
    __syncthreads();

    int warp = tid >> 5, lane = tid & 31;
    for (int it = 0; it < 5; it++) {
        int pp = warp * 5 + it;          // 0..39 = (h, j)
        int h = pp / KNB, j = pp % KNB;
        size_t r = (size_t)m * KNB + j;
        const float* krow = p.kv + r * (2 * QD) + h * HD;
        float s = 0.f;
        for (int d = lane; d < HD; d += 32) s += sq[h * HD + d] * krow[d];
        for (int o = 16; o > 0; o >>= 1) s += __shfl_down_sync(0xffffffffu, s, o);
        if (lane == 0) {
            int nid = (m < p.split_m) ? p.ids1[(size_t)m * KNB + j]
                                      : p.ids2[(size_t)(m - p.split_m) * KNB + j];
            sscore[h][j] = (nid == 0) ? -1e10f : s * SCALE;
        }
    }
    __syncthreads();

    if (tid < NH) {
        int h = tid;
        float mx = -INFINITY;
        for (int j = 0; j < KNB; j++) mx = fmaxf(mx, sscore[h][j]);
        float e[KNB], sum = 0.f;
        for (int j = 0; j < KNB; j++) { e[j] = expf(sscore[h][j] - mx); sum += e[j]; }
        float inv = 1.f / sum;
        for (int j = 0; j < KNB; j++) satt[h][j] = e[j] * inv;
    }
    __syncthreads();

    for (int c = tid; c < QD; c += 256) {
        int h = c / HD;
        const float* vbase = p.kv + (size_t)m * KNB * (2 * QD) + QD + c;
        float acc = 0.f;
#pragma unroll
        for (int j = 0; j < KNB; j++) acc += satt[h][j] * vbase[(size_t)j * (2 * QD)];
        p.out[(size_t)m * QD + c] = acc;
    }
}

__global__ __launch_bounds__(256) void ln_k(float* x, const float* g, const float* b) {
    int m = blockIdx.x, tid = threadIdx.x;
    float* row = x + (size_t)m * QD;
    __shared__ float red[256];
    __shared__ float s_mu, s_inv;
    float s = 0.f;
    for (int c = tid; c < QD; c += 256) s += row[c];
    red[tid] = s; __syncthreads();
    for (int o = 128; o > 0; o >>= 1) { if (tid < o) red[tid] += red[tid + o]; __syncthreads(); }
    if (tid == 0) s_mu = red[0] / (float)QD;
    __syncthreads();
    float mu = s_mu, v = 0.f;
    for (int c = tid; c < QD; c += 256) { float d = row[c] - mu; v += d * d; }
    red[tid] = v; __syncthreads();
    for (int o = 128; o > 0; o >>= 1) { if (tid < o) red[tid] += red[tid + o]; __syncthreads(); }
    if (tid == 0) s_inv = 1.0f / sqrtf(red[0] / (float)QD + 1e-5f);
    __syncthreads();
    float inv = s_inv;
    for (int c = tid; c < QD; c += 256)
        row[c] = (row[c] - mu) * inv * g[c] + b[c];
}

// ---------------- host ----------------
static inline dim3 gemm_grid(int M, int N) {
    return dim3((N + 127) / 128, (M + 127) / 128);
}

extern "C" void kernel_launch(void* const* d_in, const int* in_sizes, int n_in,
                              void* d_out, int out_size) {
    const float* node_raw = (const float*)d_in[0];
    const float* edge_raw = (const float*)d_in[1];
    const float* memories = (const float*)d_in[2];
    const float* t_node   = (const float*)d_in[3];
    const float* t_n1     = (const float*)d_in[4];
    const float* t_n2     = (const float*)d_in[5];
    const float* time_w   = (const float*)d_in[6];
    const float* time_b   = (const float*)d_in[7];
    const float* Wq       = (const float*)d_in[8];
    const float* Wk       = (const float*)d_in[9];
    const float* Wv       = (const float*)d_in[10];
    const float* Wo       = (const float*)d_in[11];
    const float* bo       = (const float*)d_in[12];
    const float* ln_g     = (const float*)d_in[13];
    const float* ln_b     = (const float*)d_in[14];
    const float* m_w1     = (const float*)d_in[15];
    const float* m_b1     = (const float*)d_in[16];
    const float* m_w2     = (const float*)d_in[17];
    const float* m_b2     = (const float*)d_in[18];
    const int* node_ids   = (const int*)d_in[19];
    const int* n1_ids     = (const int*)d_in[20];
    const int* n1_eids    = (const int*)d_in[21];
    const int* n2_ids     = (const int*)d_in[22];
    const int* n2_eids    = (const int*)d_in[23];
    float* out = (float*)d_out;

    float *kvout, *wkv, *qin, *q, *attout, *x, *h, *l1out, *qin2;
    cudaGetSymbolAddress((void**)&kvout,  g_kvout);
    cudaGetSymbolAddress((void**)&wkv,    g_wkv);
    cudaGetSymbolAddress((void**)&qin,    g_qin);
    cudaGetSymbolAddress((void**)&q,      g_q);
    cudaGetSymbolAddress((void**)&attout, g_attout);
    cudaGetSymbolAddress((void**)&x,      g_x);
    cudaGetSymbolAddress((void**)&h,      g_h);
    cudaGetSymbolAddress((void**)&l1out,  g_l1out);
    cudaGetSymbolAddress((void**)&qin2,   g_qin2);

    const int WKV_ELEMS = KDIM * 2 * QD;

    // ================= layer 1 (both calls merged: M1T rows) =================
    concat_wkv_k<<<(WKV_ELEMS + 255) / 256, 256>>>(Wk, Wv, wkv);
    build_qin1_k<<<M1T, QD>>>(memories, node_raw, node_ids, n1_ids, time_b, qin);

    // KV projection with fused gather: (R1T x 444) @ (444 x 544)
    {
        GemmP p = {};
        p.M = R1T; p.N = 2 * QD; p.Kd = KDIM;
        p.Bm = wkv; p.ldb = 2 * QD;
        p.C = kvout; p.ldc = 2 * QD;
        p.g.memories = memories; p.g.node_raw = node_raw; p.g.edge_raw = edge_raw;
        p.g.conv_rows = nullptr;
        p.g.ids1 = n1_ids;  p.g.ids2 = n2_ids;
        p.g.eids1 = n1_eids; p.g.eids2 = n2_eids;
        p.g.nt1 = t_n1; p.g.nt2 = t_n2;
        p.g.t1 = t_node; p.g.t2 = t_n1;
        p.g.time_w = time_w; p.g.time_b = time_b;
        p.g.split_m = B_;
        mma_gemm_k<1><<<gemm_grid(p.M, p.N), 256>>>(p);
    }
    // Q projection
    {
        GemmP p = {};
        p.M = M1T; p.N = QD; p.Kd = QD;
        p.A = qin; p.lda = QD;
        p.Bm = Wq; p.ldb = QD;
        p.C = q; p.ldc = QD;
        mma_gemm_k<0><<<gemm_grid(p.M, p.N), 256>>>(p);
    }
    // attention
    {
        AttnP ap = { q, kvout, attout, n1_ids, n2_ids, B_ };
        attn_k<<<M1T, 256>>>(ap);
    }
    // out-proj + bias + residual, then LN
    {
        GemmP p = {};
        p.M = M1T; p.N = QD; p.Kd = QD;
        p.A = attout; p.lda = QD;
        p.Bm = Wo; p.ldb = QD;
        p.C = x; p.ldc = QD;
        p.bias = bo; p.res = qin; p.ldres = QD;
        mma_gemm_k<0><<<gemm_grid(p.M, p.N), 256>>>(p);
    }
    ln_k<<<M1T, 256>>>(x, ln_g, ln_b);
    // merge fc1: relu([x | nf] @ m_w1 + b1), nf = qin[:, 0:172]
    {
        GemmP p = {};
        p.M = M1T; p.N = DN; p.Kd = QD + DN;
        p.A = x; p.lda = QD;
        p.A2 = qin; p.lda2 = QD; p.split = QD;
        p.Bm = m_w1; p.ldb = DN;
        p.C = h; p.ldc = DN;
        p.bias = m_b1; p.relu = 1;
        mma_gemm_k<2><<<gemm_grid(p.M, p.N), 256>>>(p);
    }
    // merge fc2 -> layer-1 conv output
    {
        GemmP p = {};
        p.M = M1T; p.N = DN; p.Kd = DN;
        p.A = h; p.lda = DN;
        p.Bm = m_w2; p.ldb = DN;
        p.C = l1out; p.ldc = DN;
        p.bias = m_b2;
        mma_gemm_k<0><<<gemm_grid(p.M, p.N), 256>>>(p);
    }

    // ================= layer 2 (M = B_) =================
    concat_wkv_k<<<(WKV_ELEMS + 255) / 256, 256>>>(Wk + (size_t)KDIM * QD,
                                                   Wv + (size_t)KDIM * QD, wkv);
    build_qin2_k<<<M2T, QD>>>(l1out, time_b, qin2);

    // KV projection: conv features come from l1out rows B_.. (layer-1 call-2 outputs)
    {
        GemmP p = {};
        p.M = R2T; p.N = 2 * QD; p.Kd = KDIM;
        p.Bm = wkv; p.ldb = 2 * QD;
        p.C = kvout; p.ldc = 2 * QD;
        p.g.memories = memories; p.g.node_raw = node_raw; p.g.edge_raw = edge_raw;
        p.g.conv_rows = l1out + (size_t)B_ * DN;
        p.g.ids1 = n1_ids;  p.g.ids2 = n1_ids;
        p.g.eids1 = n1_eids; p.g.eids2 = n1_eids;
        p.g.nt1 = t_n1; p.g.nt2 = t_n1;
        p.g.t1 = t_node; p.g.t2 = t_node;
        p.g.time_w = time_w; p.g.time_b = time_b;
        p.g.split_m = B_;   // all rows use the *1 arrays
        mma_gemm_k<1><<<gemm_grid(p.M, p.N), 256>>>(p);
    }
    {
        GemmP p = {};
        p.M = M2T; p.N = QD; p.Kd = QD;
        p.A = qin2; p.lda = QD;
        p.Bm = Wq + (size_t)QD * QD; p.ldb = QD;
        p.C = q; p.ldc = QD;
        mma_gemm_k<0><<<gemm_grid(p.M, p.N), 256>>>(p);
    }
    {
        AttnP ap = { q, kvout, attout, n1_ids, n1_ids, B_ };
        attn_k<<<M2T, 256>>>(ap);
    }
    {
        GemmP p = {};
        p.M = M2T; p.N = QD; p.Kd = QD;
        p.A = attout; p.lda = QD;
        p.Bm = Wo + (size_t)QD * QD; p.ldb = QD;
        p.C = x; p.ldc = QD;
        p.bias = bo + QD; p.res = qin2; p.ldres = QD;
        mma_gemm_k<0><<<gemm_grid(p.M, p.N), 256>>>(p);
    }
    ln_k<<<M2T, 256>>>(x, ln_g + QD, ln_b + QD);
    // final merge: x2 = nf = memories[node_ids]+node_raw[node_ids] = qin rows 0..B_-1, cols 0..171
    {
        GemmP p = {};
        p.M = M2T; p.N = DN; p.Kd = QD + DN;
        p.A = x; p.lda = QD;
        p.A2 = qin; p.lda2 = QD; p.split = QD;
        p.Bm = m_w1 + (size_t)(QD + DN) * DN; p.ldb = DN;
        p.C = h; p.ldc = DN;
        p.bias = m_b1 + DN; p.relu = 1;
        mma_gemm_k<2><<<gemm_grid(p.M, p.N), 256>>>(p);
    }
    {
        GemmP p = {};
        p.M = M2T; p.N = DN; p.Kd = DN;
        p.A = h; p.lda = DN;
        p.Bm = m_w2 + (size_t)DN * DN; p.ldb = DN;
        p.C = out; p.ldc = DN;
        p.bias = m_b2 + DN;
        mma_gemm_k<0><<<gemm_grid(p.M, p.N), 256>>>(p);
    }
    (void)in_sizes; (void)n_in; (void)out_size;
}

// round 14
// speedup vs baseline: 1.0052x; 1.0052x over previous
#include <cuda_runtime.h>
#include <cuda_bf16.h>
#include <math.h>

// ---------------- problem constants ----------------
#define B_    1024
#define KNB   20
#define DN    172
#define DE    172
#define DT    100
#define QD    272          // DN + DT
#define KDIM  444          // DN + DE + DT
#define HD    136          // QD / 2 heads
#define NH    2
#define M1T   (B_ + B_*KNB)        // 21504 rows for layer-1 (both calls merged)
#define R1T   (M1T*KNB)            // 430080 kv rows
#define M2T   B_
#define R2T   (B_*KNB)             // 20480

// ---------------- scratch (device globals; no allocation allowed) ----------------
__device__ float g_kvout[(size_t)R1T * (2*QD)];   // K|V concat, 544 per row (~936 MB)
__device__ float g_wkv[KDIM * 2*QD];              // [Wk|Wv] concat per layer
__device__ float g_qin[(size_t)M1T * QD];         // layer-1 q_in (also residual + nf)
__device__ float g_q[(size_t)M1T * QD];
__device__ float g_attout[(size_t)M1T * QD];
__device__ float g_x[(size_t)M1T * QD];
__device__ float g_h[(size_t)M1T * DN];
__device__ float g_l1out[(size_t)M1T * DN];       // layer-1 conv output (kept for layer 2)
__device__ float g_qin2[(size_t)M2T * QD];

// ---------------- gather descriptor for the fused KV GEMM ----------------
struct KvGather {
    const float* memories;
    const float* node_raw;
    const float* edge_raw;
    const float* conv_rows;   // layer 2: conv features come from here (row r)
    const int*   ids1;  const int*   ids2;    // neighbor ids  (split by m)
    const int*   eids1; const int*   eids2;   // edge ids
    const float* nt1;   const float* nt2;     // neighbor times
    const float* t1;    const float* t2;      // center times
    const float* time_w; const float* time_b;
    int split_m;
};

struct GemmP {
    int M, N, Kd;
    const float* A;  int lda;      // MODE 0 / MODE 2 first part
    const float* A2; int lda2; int split;   // MODE 2 second part
    const float* Bm; int ldb;      // weights, Kd x N row-major
    float* C; int ldc;
    const float* bias;             // may be null
    const float* res; int ldres;   // may be null
    int relu;
    KvGather g;                    // MODE 1
};

__device__ __forceinline__ float kv_elem(const KvGather& g, int r, int k) {
    int m = r / KNB;
    if (k < DN) {
        if (g.conv_rows) return g.conv_rows[(size_t)r * DN + k];
        int id = (m < g.split_m) ? g.ids1[r] : g.ids2[r - g.split_m * KNB];
        return g.memories[(size_t)id * DN + k] + g.node_raw[(size_t)id * DN + k];
    } else if (k < DN + DE) {
        int eid = (m < g.split_m) ? g.eids1[r] : g.eids2[r - g.split_m * KNB];
        return g.edge_raw[(size_t)eid * DE + (k - DN)];
    } else {
        float tc = (m < g.split_m) ? g.t1[m] : g.t2[m - g.split_m];
        float tn = (m < g.split_m) ? g.nt1[r] : g.nt2[r - g.split_m * KNB];
        float dt = tc - tn;
        int j = k - DN - DE;
        return cosf(dt * g.time_w[j] + g.time_b[j]);
    }
}

template<int MODE>
__device__ __forceinline__ float load_a(const GemmP& p, int row, int k) {
    if (MODE == 0) return p.A[(size_t)row * p.lda + k];
    if (MODE == 2) return (k < p.split) ? p.A[(size_t)row * p.lda + k]
                                        : p.A2[(size_t)row * p.lda2 + (k - p.split)];
    return kv_elem(p.g, row, k);   // MODE 1
}

// ---------------- tf32 tensor-core GEMM ----------------
__device__ __forceinline__ unsigned f2tf32(float x) {
    unsigned u;
    asm("cvt.rna.tf32.f32 %0, %1;" : "=r"(u) : "f"(x));
    return u;
}

__device__ __forceinline__ void mma8(float* c, const unsigned* a, const unsigned* b) {
    asm volatile(
        "mma.sync.aligned.m16n8k8.row.col.f32.tf32.tf32.f32 "
        "{%0,%1,%2,%3}, {%4,%5,%6,%7}, {%8,%9}, {%0,%1,%2,%3};"
        : "+f"(c[0]), "+f"(c[1]), "+f"(c[2]), "+f"(c[3])
        : "r"(a[0]), "r"(a[1]), "r"(a[2]), "r"(a[3]), "r"(b[0]), "r"(b[1]));
}

template<int MODE>
__device__ __forceinline__ void g_fetch(const GemmP& p, int kt, int arow, bool aok,
                                        int bcol, bool cok, int fkb,
                                        float* areg, float* breg) {
#pragma unroll
    for (int i = 0; i < 8; i++) {
        int k = kt * 16 + fkb + i;
        bool kok = k < p.Kd;
        areg[i] = (kok && aok) ? load_a<MODE>(p, arow, k) : 0.f;
        breg[i] = (kok && cok) ? p.Bm[(size_t)k * p.ldb + bcol] : 0.f;
    }
}

__device__ __forceinline__ void s_store(unsigned A[16][136], unsigned Bsh[16][136],
                                        int fkb, int fm,
                                        const float* areg, const float* breg) {
#pragma unroll
    for (int i = 0; i < 8; i++) {
        A[fkb + i][fm]   = f2tf32(areg[i]);
        Bsh[fkb + i][fm] = f2tf32(breg[i]);
    }
}

// 128x128x16 block tile, 256 threads (8 warps, 2x4), warp tile 64x32 of m16n8k8.
template<int MODE>
__global__ __launch_bounds__(256) void mma_gemm_k(GemmP p) {
    __shared__ unsigned As[2][16][136];
    __shared__ unsigned Bs[2][16][136];
    const int tid  = threadIdx.x;
    const int bm   = blockIdx.y * 128;
    const int bn   = blockIdx.x * 128;
    const int warp = tid >> 5, lane = tid & 31;
    const int wm = warp >> 2, wn = warp & 3;
    const int gid = lane >> 2, qid = lane & 3;
    const int fm  = tid & 127;
    const int fkb = (tid >> 7) << 3;          // 0 or 8

    float acc[4][4][4];
#pragma unroll
    for (int i = 0; i < 4; i++)
#pragma unroll
        for (int j = 0; j < 4; j++)
#pragma unroll
            for (int r = 0; r < 4; r++) acc[i][j][r] = 0.f;

    const int arow = bm + fm;
    const int bcol = bn + fm;
    const bool aok = arow < p.M;
    const bool cok = bcol < p.N;
    const int nkt = (p.Kd + 15) >> 4;

    float areg[8], breg[8];
    g_fetch<MODE>(p, 0, arow, aok, bcol, cok, fkb, areg, breg);
    s_store(As[0], Bs[0], fkb, fm, areg, breg);
    __syncthreads();

    for (int kt = 0; kt < nkt; kt++) {
        const int buf = kt & 1;
        if (kt + 1 < nkt)
            g_fetch<MODE>(p, kt + 1, arow, aok, bcol, cok, fkb, areg, breg);

#pragma unroll
        for (int ks = 0; ks < 2; ks++) {
            unsigned af[4][4], bf[4][2];
#pragma unroll
            for (int mt = 0; mt < 4; mt++) {
                int m0 = wm * 64 + mt * 16 + gid;
                af[mt][0] = As[buf][ks * 8 + qid    ][m0];
                af[mt][1] = As[buf][ks * 8 + qid    ][m0 + 8];
                af[mt][2] = As[buf][ks * 8 + qid + 4][m0];
                af[mt][3] = As[buf][ks * 8 + qid + 4][m0 + 8];
            }
#pragma unroll
            for (int nt = 0; nt < 4; nt++) {
                int n0 = wn * 32 + nt * 8 + gid;
                bf[nt][0] = Bs[buf][ks * 8 + qid    ][n0];
                bf[nt][1] = Bs[buf][ks * 8 + qid + 4][n0];
            }
#pragma unroll
            for (int mt = 0; mt < 4; mt++)
#pragma unroll
                for (int nt = 0; nt < 4; nt++)
                    mma8(acc[mt][nt], af[mt], bf[nt]);
        }

        if (kt + 1 < nkt) {
            s_store(As[buf ^ 1], Bs[buf ^ 1], fkb, fm, areg, breg);
            __syncthreads();
        }
    }

    // epilogue: c0/c1 = (row gid, cols 2q,2q+1); c2/c3 = row gid+8
#pragma unroll
    for (int mt = 0; mt < 4; mt++) {
#pragma unroll
        for (int half = 0; half < 2; half++) {
            int row = bm + wm * 64 + mt * 16 + gid + half * 8;
            if (row >= p.M) continue;
#pragma unroll
            for (int nt = 0; nt < 4; nt++) {
                int col = bn + wn * 32 + nt * 8 + 2 * qid;
                if (col >= p.N) continue;        // N is even, so col+1 < N too
                float v0 = acc[mt][nt][half * 2 + 0];
                float v1 = acc[mt][nt][half * 2 + 1];
                if (p.bias) { v0 += p.bias[col]; v1 += p.bias[col + 1]; }
                if (p.res)  { v0 += p.res[(size_t)row * p.ldres + col];
                              v1 += p.res[(size_t)row * p.ldres + col + 1]; }
                if (p.relu) { v0 = fmaxf(v0, 0.f); v1 = fmaxf(v1, 0.f); }
                *reinterpret_cast<float2*>(&p.C[(size_t)row * p.ldc + col]) =
                    make_float2(v0, v1);
            }
        }
    }
}

// ---------------- small kernels ----------------
__global__ void concat_wkv_k(const float* Wk, const float* Wv, float* dst) {
    int idx = blockIdx.x * 256 + threadIdx.x;
    if (idx >= KDIM * 2 * QD) return;
    int k = idx / (2 * QD), n = idx % (2 * QD);
    dst[idx] = (n < QD) ? Wk[(size_t)k * QD + n] : Wv[(size_t)k * QD + (n - QD)];
}

__global__ void build_qin1_k(const float* mem, const float* raw,
                             const int* node_ids, const int* n1_ids,
                             const float* time_b, float* qin) {
    int m = blockIdx.x, c = threadIdx.x;   // 272 threads
    int id = (m < B_) ? node_ids[m] : n1_ids[m - B_];
    float v;
    if (c < DN) v = mem[(size_t)id * DN + c] + raw[(size_t)id * DN + c];
    else        v = cosf(time_b[c - DN]);
    qin[(size_t)m * QD + c] = v;
}

__global__ void build_qin2_k(const float* l1out, const float* time_b, float* qin) {
    int m = blockIdx.x, c = threadIdx.x;
    qin[(size_t)m * QD + c] = (c < DN) ? l1out[(size_t)m * DN + c]
                                       : cosf(time_b[c - DN]);
}

struct AttnP {
    const float* q;    // M x 272
    const float* kv;   // (M*20) x 544
    float* out;        // M x 272
    const int* ids1; const int* ids2; int split_m;
};

__global__ __launch_bounds__(256) void attn_k(AttnP p) {
    const float SCALE = 0.08574929257125441669f;   // 136^-0.5
    int m = blockIdx.x;
    __shared__ float sq[QD];
    __shared__ float sscore[NH][KNB];
    __shared__ float satt[NH][KNB];
    int tid = threadIdx.x;
    for (int c = tid; c < QD; c += 256) sq[c] = p.q[(size_t)m * QD + c];
    __syncthreads();

    int warp = tid >> 5, lane = tid & 31;
    for (int it = 0; it < 5; it++) {
        int pp = warp * 5 + it;          // 0..39 = (h, j)
        int h = pp / KNB, j = pp % KNB;
        size_t r = (size_t)m * KNB + j;
        const float* krow = p.kv + r * (2 * QD) + h * HD;
        float s = 0.f;
        for (int d = lane; d < HD; d += 32) s += sq[h * HD + d] * krow[d];
        for (int o = 16; o > 0; o >>= 1) s += __shfl_down_sync(0xffffffffu, s, o);
        if (lane == 0) {
            int nid = (m < p.split_m) ? p.ids1[(size_t)m * KNB + j]
                                      : p.ids2[(size_t)(m - p.split_m) * KNB + j];
            sscore[h][j] = (nid == 0) ? -1e10f : s * SCALE;
        }
    }
    __syncthreads();

    if (tid < NH) {
        int h = tid;
        float mx = -INFINITY;
        for (int j = 0; j < KNB; j++) mx = fmaxf(mx, sscore[h][j]);
        float e[KNB], sum = 0.f;
        for (int j = 0; j < KNB; j++) { e[j] = expf(sscore[h][j] - mx); sum += e[j]; }
        float inv = 1.f / sum;
        for (int j = 0; j < KNB; j++) satt[h][j] = e[j] * inv;
    }
    __syncthreads();

    for (int c = tid; c < QD; c += 256) {
        int h = c / HD;
        const float* vbase = p.kv + (size_t)m * KNB * (2 * QD) + QD + c;
        float acc = 0.f;
#pragma unroll
        for (int j = 0; j < KNB; j++) acc += satt[h][j] * vbase[(size_t)j * (2 * QD)];
        p.out[(size_t)m * QD + c] = acc;
    }
}

__global__ __launch_bounds__(256) void ln_k(float* x, const float* g, const float* b) {
    int m = blockIdx.x, tid = threadIdx.x;
    float* row = x + (size_t)m * QD;
    __shared__ float red[256];
    __shared__ float s_mu, s_inv;
    float s = 0.f;
    for (int c = tid; c < QD; c += 256) s += row[c];
    red[tid] = s; __syncthreads();
    for (int o = 128; o > 0; o >>= 1) { if (tid < o) red[tid] += red[tid + o]; __syncthreads(); }
    if (tid == 0) s_mu = red[0] / (float)QD;
    __syncthreads();
    float mu = s_mu, v = 0.f;
    for (int c = tid; c < QD; c += 256) { float d = row[c] - mu; v += d * d; }
    red[tid] = v; __syncthreads();
    for (int o = 128; o > 0; o >>= 1) { if (tid < o) red[tid] += red[tid + o]; __syncthreads(); }
    if (tid == 0) s_inv = 1.0f / sqrtf(red[0] / (float)QD + 1e-5f);
    __syncthreads();
    float inv = s_inv;
    for (int c = tid; c < QD; c += 256)
        row[c] = (row[c] - mu) * inv * g[c] + b[c];
}

// ---------------- host ----------------
static inline dim3 gemm_grid(int M, int N) {
    return dim3((N + 127) / 128, (M + 127) / 128);
}

extern "C" void kernel_launch(void* const* d_in, const int* in_sizes, int n_in,
                              void* d_out, int out_size) {
    const float* node_raw = (const float*)d_in[0];
    const float* edge_raw = (const float*)d_in[1];
    const float* memories = (const float*)d_in[2];
    const float* t_node   = (const float*)d_in[3];
    const float* t_n1     = (const float*)d_in[4];
    const float* t_n2     = (const float*)d_in[5];
    const float* time_w   = (const float*)d_in[6];
    const float* time_b   = (const float*)d_in[7];
    const float* Wq       = (const float*)d_in[8];
    const float* Wk       = (const float*)d_in[9];
    const float* Wv       = (const float*)d_in[10];
    const float* Wo       = (const float*)d_in[11];
    const float* bo       = (const float*)d_in[12];
    const float* ln_g     = (const float*)d_in[13];
    const float* ln_b     = (const float*)d_in[14];
    const float* m_w1     = (const float*)d_in[15];
    const float* m_b1     = (const float*)d_in[16];
    const float* m_w2     = (const float*)d_in[17];
    const float* m_b2     = (const float*)d_in[18];
    const int* node_ids   = (const int*)d_in[19];
    const int* n1_ids     = (const int*)d_in[20];
    const int* n1_eids    = (const int*)d_in[21];
    const int* n2_ids     = (const int*)d_in[22];
    const int* n2_eids    = (const int*)d_in[23];
    float* out = (float*)d_out;

    float *kvout, *wkv, *qin, *q, *attout, *x, *h, *l1out, *qin2;
    cudaGetSymbolAddress((void**)&kvout,  g_kvout);
    cudaGetSymbolAddress((void**)&wkv,    g_wkv);
    cudaGetSymbolAddress((void**)&qin,    g_qin);
    cudaGetSymbolAddress((void**)&q,      g_q);
    cudaGetSymbolAddress((void**)&attout, g_attout);
    cudaGetSymbolAddress((void**)&x,      g_x);
    cudaGetSymbolAddress((void**)&h,      g_h);
    cudaGetSymbolAddress((void**)&l1out,  g_l1out);
    cudaGetSymbolAddress((void**)&qin2,   g_qin2);

    const int WKV_ELEMS = KDIM * 2 * QD;

    // ================= layer 1 (both calls merged: M1T rows) =================
    concat_wkv_k<<<(WKV_ELEMS + 255) / 256, 256>>>(Wk, Wv, wkv);
    build_qin1_k<<<M1T, QD>>>(memories, node_raw, node_ids, n1_ids, time_b, qin);

    // KV projection with fused gather: (R1T x 444) @ (444 x 544)
    {
        GemmP p = {};
        p.M = R1T; p.N = 2 * QD; p.Kd = KDIM;
        p.Bm = wkv; p.ldb = 2 * QD;
        p.C = kvout; p.ldc = 2 * QD;
        p.g.memories = memories; p.g.node_raw = node_raw; p.g.edge_raw = edge_raw;
        p.g.conv_rows = nullptr;
        p.g.ids1 = n1_ids;  p.g.ids2 = n2_ids;
        p.g.eids1 = n1_eids; p.g.eids2 = n2_eids;
        p.g.nt1 = t_n1; p.g.nt2 = t_n2;
        p.g.t1 = t_node; p.g.t2 = t_n1;
        p.g.time_w = time_w; p.g.time_b = time_b;
        p.g.split_m = B_;
        mma_gemm_k<1><<<gemm_grid(p.M, p.N), 256>>>(p);
    }
    // Q projection
    {
        GemmP p = {};
        p.M = M1T; p.N = QD; p.Kd = QD;
        p.A = qin; p.lda = QD;
        p.Bm = Wq; p.ldb = QD;
        p.C = q; p.ldc = QD;
        mma_gemm_k<0><<<gemm_grid(p.M, p.N), 256>>>(p);
    }
    // attention
    {
        AttnP ap = { q, kvout, attout, n1_ids, n2_ids, B_ };
        attn_k<<<M1T, 256>>>(ap);
    }
    // out-proj + bias + residual, then LN
    {
        GemmP p = {};
        p.M = M1T; p.N = QD; p.Kd = QD;
        p.A = attout; p.lda = QD;
        p.Bm = Wo; p.ldb = QD;
        p.C = x; p.ldc = QD;
        p.bias = bo; p.res = qin; p.ldres = QD;
        mma_gemm_k<0><<<gemm_grid(p.M, p.N), 256>>>(p);
    }
    ln_k<<<M1T, 256>>>(x, ln_g, ln_b);
    // merge fc1: relu([x | nf] @ m_w1 + b1), nf = qin[:, 0:172]
    {
        GemmP p = {};
        p.M = M1T; p.N = DN; p.Kd = QD + DN;
        p.A = x; p.lda = QD;
        p.A2 = qin; p.lda2 = QD; p.split = QD;
        p.Bm = m_w1; p.ldb = DN;
        p.C = h; p.ldc = DN;
        p.bias = m_b1; p.relu = 1;
        mma_gemm_k<2><<<gemm_grid(p.M, p.N), 256>>>(p);
    }
    // merge fc2 -> layer-1 conv output
    {
        GemmP p = {};
        p.M = M1T; p.N = DN; p.Kd = DN;
        p.A = h; p.lda = DN;
        p.Bm = m_w2; p.ldb = DN;
        p.C = l1out; p.ldc = DN;
        p.bias = m_b2;
        mma_gemm_k<0><<<gemm_grid(p.M, p.N), 256>>>(p);
    }

    // ================= layer 2 (M = B_) =================
    concat_wkv_k<<<(WKV_ELEMS + 255) / 256, 256>>>(Wk + (size_t)KDIM * QD,
                                                   Wv + (size_t)KDIM * QD, wkv);
    build_qin2_k<<<M2T, QD>>>(l1out, time_b, qin2);

    // KV projection: conv features come from l1out rows B_.. (layer-1 call-2 outputs)
    {
        GemmP p = {};
        p.M = R2T; p.N = 2 * QD; p.Kd = KDIM;
        p.Bm = wkv; p.ldb = 2 * QD;
        p.C = kvout; p.ldc = 2 * QD;
        p.g.memories = memories; p.g.node_raw = node_raw; p.g.edge_raw = edge_raw;
        p.g.conv_rows = l1out + (size_t)B_ * DN;
        p.g.ids1 = n1_ids;  p.g.ids2 = n1_ids;
        p.g.eids1 = n1_eids; p.g.eids2 = n1_eids;
        p.g.nt1 = t_n1; p.g.nt2 = t_n1;
        p.g.t1 = t_node; p.g.t2 = t_node;
        p.g.time_w = time_w; p.g.time_b = time_b;
        p.g.split_m = B_;   // all rows use the *1 arrays
        mma_gemm_k<1><<<gemm_grid(p.M, p.N), 256>>>(p);
    }
    {
        GemmP p = {};
        p.M = M2T; p.N = QD; p.Kd = QD;
        p.A = qin2; p.lda = QD;
        p.Bm = Wq + (size_t)QD * QD; p.ldb = QD;
        p.C = q; p.ldc = QD;
        mma_gemm_k<0><<<gemm_grid(p.M, p.N), 256>>>(p);
    }
    {
        AttnP ap = { q, kvout, attout, n1_ids, n1_ids, B_ };
        attn_k<<<M2T, 256>>>(ap);
    }
    {
        GemmP p = {};
        p.M = M2T; p.N = QD; p.Kd = QD;
        p.A = attout; p.lda = QD;
        p.Bm = Wo + (size_t)QD * QD; p.ldb = QD;
        p.C = x; p.ldc = QD;
        p.bias = bo + QD; p.res = qin2; p.ldres = QD;
        mma_gemm_k<0><<<gemm_grid(p.M, p.N), 256>>>(p);
    }
    ln_k<<<M2T, 256>>>(x, ln_g + QD, ln_b + QD);
    // final merge: x2 = nf = memories[node_ids]+node_raw[node_ids] = qin rows 0..B_-1, cols 0..171
    {
        GemmP p = {};
        p.M = M2T; p.N = DN; p.Kd = QD + DN;
        p.A = x; p.lda = QD;
        p.A2 = qin; p.lda2 = QD; p.split = QD;
        p.Bm = m_w1 + (size_t)(QD + DN) * DN; p.ldb = DN;
        p.C = h; p.ldc = DN;
        p.bias = m_b1 + DN; p.relu = 1;
        mma_gemm_k<2><<<gemm_grid(p.M, p.N), 256>>>(p);
    }
    {
        GemmP p = {};
        p.M = M2T; p.N = DN; p.Kd = DN;
        p.A = h; p.lda = DN;
        p.Bm = m_w2 + (size_t)DN * DN; p.ldb = DN;
        p.C = out; p.ldc = DN;
        p.bias = m_b2 + DN;
        mma_gemm_k<0><<<gemm_grid(p.M, p.N), 256>>>(p);
    }
    (void)in_sizes; (void)n_in; (void)out_size;
}